// round 2
// baseline (speedup 1.0000x reference)
#include <cuda_runtime.h>
#include <math.h>

#define T_STEPS 256
#define BATCH   128
#define IN_SZ   512
#define HID     1024
#define OUT_SZ  512
#define G4      4096   // 4 gates * HID, interleaved col = 4*j + g  (g: 0=f,1=i,2=c,3=o)
#define NROWS   (T_STEPS*BATCH)   // 32768
#define LSTM_BLOCKS 128

// ---- static device scratch (no allocations allowed) ----
__device__ float d_xproj[NROWS * G4];          // 512 MB: pre-activation input part + bias, [t*128+b][4j+g]
__device__ float d_hs[BATCH * T_STEPS * HID];  // 128 MB: hidden states [b][t][j]
__device__ float d_Hbuf[2 * HID * BATCH];      // ping-pong h, layout [buf][j][b]
__device__ float d_Wri[HID * G4];              // recurrent weights, [k][4j+g]
__device__ float d_Wxi[IN_SZ * G4];            // input weights,     [k][4j+g]
__device__ float d_bi[G4];                     // interleaved bias
__device__ float d_Wot[HID * OUT_SZ];          // W_out^T: [k][o]
__device__ unsigned long long d_bar;           // monotone grid-barrier counter

// -------------------- packing kernels --------------------
__global__ void pack_w(const float* __restrict__ Wf, const float* __restrict__ Wi,
                       const float* __restrict__ Wc, const float* __restrict__ Wo) {
    int idx = blockIdx.x * blockDim.x + threadIdx.x;      // over 1536*4096
    if (idx >= 1536 * G4) return;
    int n = idx & (G4 - 1);
    int k = idx >> 12;
    int g = n & 3, j = n >> 2;
    const float* W = (g == 0) ? Wf : (g == 1) ? Wi : (g == 2) ? Wc : Wo;
    float v = W[j * 1536 + k];
    if (k < IN_SZ) d_Wxi[k * G4 + n] = v;
    else           d_Wri[(k - IN_SZ) * G4 + n] = v;
}

__global__ void pack_misc(const float* __restrict__ bf, const float* __restrict__ bi_,
                          const float* __restrict__ bc, const float* __restrict__ bo,
                          const float* __restrict__ Wout) {
    int idx = blockIdx.x * blockDim.x + threadIdx.x;
    if (idx < HID * OUT_SZ) {
        int k = idx / OUT_SZ, o = idx % OUT_SZ;
        d_Wot[idx] = Wout[o * HID + k];
    }
    if (idx < 2 * HID * BATCH) d_Hbuf[idx] = 0.f;
    if (idx < G4) {
        int g = idx & 3, j = idx >> 2;
        const float* b = (g == 0) ? bf : (g == 1) ? bi_ : (g == 2) ? bc : bo;
        d_bi[idx] = b[j];
    }
}

// -------------------- input projection GEMM --------------------
// C[r][n] = sum_k x_row(r)[k] * Wxi[k][n] + bi[n],  r = t*128 + b, x row ptr = x + (b*256+t)*512
__global__ void xproj_kernel(const float* __restrict__ x) {
    __shared__ __align__(16) float As[32][68];
    __shared__ __align__(16) float Bs[32][64];
    int n0 = blockIdx.x * 64;
    int r0 = blockIdx.y * 64;
    int tm = threadIdx.x >> 4, tn = threadIdx.x & 15;
    float acc[4][4];
#pragma unroll
    for (int i = 0; i < 4; i++)
#pragma unroll
        for (int j = 0; j < 4; j++) acc[i][j] = 0.f;

    for (int kb = 0; kb < IN_SZ; kb += 32) {
#pragma unroll
        for (int q = 0; q < 2; q++) {
            int lin4 = threadIdx.x + q * 256;          // 0..511
            int row = lin4 >> 3, kq = (lin4 & 7) << 2;
            int r = r0 + row;
            int t = r >> 7, b = r & 127;
            float4 v = *(const float4*)(x + ((b << 8) + t) * IN_SZ + kb + kq);
            As[kq + 0][row] = v.x; As[kq + 1][row] = v.y;
            As[kq + 2][row] = v.z; As[kq + 3][row] = v.w;
        }
#pragma unroll
        for (int q = 0; q < 2; q++) {
            int lin4 = threadIdx.x + q * 256;
            int kk = lin4 >> 4, nq = (lin4 & 15) << 2;
            *(float4*)&Bs[kk][nq] = *(const float4*)(d_Wxi + (kb + kk) * G4 + n0 + nq);
        }
        __syncthreads();
#pragma unroll
        for (int kk = 0; kk < 32; kk++) {
            float4 av = *(float4*)&As[kk][tm << 2];
            float4 bv = *(float4*)&Bs[kk][tn << 2];
            float ar[4] = {av.x, av.y, av.z, av.w};
            float br[4] = {bv.x, bv.y, bv.z, bv.w};
#pragma unroll
            for (int i = 0; i < 4; i++)
#pragma unroll
                for (int j = 0; j < 4; j++) acc[i][j] += ar[i] * br[j];
        }
        __syncthreads();
    }
    float4 bias = *(const float4*)(d_bi + n0 + (tn << 2));
#pragma unroll
    for (int rm = 0; rm < 4; rm++) {
        int r = r0 + (tm << 2) + rm;
        float4 o;
        o.x = acc[rm][0] + bias.x; o.y = acc[rm][1] + bias.y;
        o.z = acc[rm][2] + bias.z; o.w = acc[rm][3] + bias.w;
        *(float4*)(d_xproj + (size_t)r * G4 + n0 + (tn << 2)) = o;
    }
}

// -------------------- persistent LSTM kernel --------------------
__device__ __forceinline__ void grid_barrier() {
    __syncthreads();
    if (threadIdx.x == 0) {
        __threadfence();
        unsigned long long ticket = atomicAdd(&d_bar, 1ULL);
        unsigned long long target = (ticket / LSTM_BLOCKS + 1ULL) * (unsigned long long)LSTM_BLOCKS;
        while (true) {
            unsigned long long v;
            asm volatile("ld.global.acquire.gpu.u64 %0, [%1];" : "=l"(v) : "l"(&d_bar));
            if (v >= target) break;
            __nanosleep(64);
        }
    }
    __syncthreads();
}

__device__ __forceinline__ float sigf(float v) { return 1.0f / (1.0f + expf(-v)); }

__global__ void __launch_bounds__(256, 1) lstm_kernel() {
    __shared__ __align__(16) float As[32][128];   // h[k][b] tile (direct copy, already transposed)
    __shared__ __align__(16) float Bs[32][32];    // Wri tile
    int jb = blockIdx.x;                 // CTA owns cols jb*32..+31  (j = jb*8+tn, 4 gates)
    int tm = threadIdx.x >> 3;           // 0..31 -> rows tm*4..+3 (batch)
    int tn = threadIdx.x & 7;            // 0..7  -> j = jb*8+tn
    int j = (jb << 3) + tn;
    float c[4] = {0.f, 0.f, 0.f, 0.f};

    for (int t = 0; t < T_STEPS; t++) {
        const float* Hread = d_Hbuf + (((t + 1) & 1) << 17);   // h_{t-1}, [j][b]
        float* Hwrite      = d_Hbuf + ((t & 1) << 17);
        float acc[4][4];
#pragma unroll
        for (int i = 0; i < 4; i++)
#pragma unroll
            for (int q = 0; q < 4; q++) acc[i][q] = 0.f;

        for (int kb = 0; kb < HID; kb += 32) {
#pragma unroll
            for (int q = 0; q < 4; q++) {
                int lin4 = threadIdx.x + q * 256;          // 0..1023 float4s
                int kk = lin4 >> 5, b4 = (lin4 & 31) << 2;
                *(float4*)&As[kk][b4] = *(const float4*)(Hread + (kb + kk) * BATCH + b4);
            }
            {
                int kk = threadIdx.x >> 3, m4 = (threadIdx.x & 7) << 2;
                *(float4*)&Bs[kk][m4] = *(const float4*)(d_Wri + (size_t)(kb + kk) * G4 + (jb << 5) + m4);
            }
            __syncthreads();
#pragma unroll
            for (int kk = 0; kk < 32; kk++) {
                float4 av = *(float4*)&As[kk][tm << 2];
                float4 bv = *(float4*)&Bs[kk][tn << 2];
                float ar[4] = {av.x, av.y, av.z, av.w};
                float br[4] = {bv.x, bv.y, bv.z, bv.w};
#pragma unroll
                for (int i = 0; i < 4; i++)
#pragma unroll
                    for (int q = 0; q < 4; q++) acc[i][q] += ar[i] * br[q];
            }
            __syncthreads();
        }

        // epilogue: add input projection, LSTM pointwise, write h_t
        float hn[4];
#pragma unroll
        for (int rm = 0; rm < 4; rm++) {
            int b = (tm << 2) + rm;
            float4 xp = *(const float4*)(d_xproj + (size_t)((t << 7) + b) * G4 + (jb << 5) + (tn << 2));
            float pf = acc[rm][0] + xp.x;
            float pi = acc[rm][1] + xp.y;
            float pc = acc[rm][2] + xp.z;
            float po = acc[rm][3] + xp.w;
            float f = sigf(pf), ig = sigf(pi), ct = tanhf(pc), og = sigf(po);
            c[rm] = f * c[rm] + ig * ct;
            hn[rm] = og * tanhf(c[rm]);
            d_hs[(size_t)(b * T_STEPS + t) * HID + j] = hn[rm];
        }
        *(float4*)(Hwrite + j * BATCH + (tm << 2)) = make_float4(hn[0], hn[1], hn[2], hn[3]);

        grid_barrier();   // h_t visible to all before step t+1 reads it
    }
}

// -------------------- output projection GEMM --------------------
// out[r][o] = sum_k hs[r][k]*Wot[k][o] + b_out[o],  r = b*256+t
__global__ void out_kernel(float* __restrict__ out, const float* __restrict__ bout) {
    __shared__ __align__(16) float As[32][68];
    __shared__ __align__(16) float Bs[32][64];
    int n0 = blockIdx.x * 64;
    int r0 = blockIdx.y * 64;
    int tm = threadIdx.x >> 4, tn = threadIdx.x & 15;
    float acc[4][4];
#pragma unroll
    for (int i = 0; i < 4; i++)
#pragma unroll
        for (int q = 0; q < 4; q++) acc[i][q] = 0.f;

    for (int kb = 0; kb < HID; kb += 32) {
#pragma unroll
        for (int q = 0; q < 2; q++) {
            int lin4 = threadIdx.x + q * 256;
            int row = lin4 >> 3, kq = (lin4 & 7) << 2;
            int r = r0 + row;
            float4 v = *(const float4*)(d_hs + (size_t)r * HID + kb + kq);
            As[kq + 0][row] = v.x; As[kq + 1][row] = v.y;
            As[kq + 2][row] = v.z; As[kq + 3][row] = v.w;
        }
#pragma unroll
        for (int q = 0; q < 2; q++) {
            int lin4 = threadIdx.x + q * 256;
            int kk = lin4 >> 4, nq = (lin4 & 15) << 2;
            *(float4*)&Bs[kk][nq] = *(const float4*)(d_Wot + (kb + kk) * OUT_SZ + n0 + nq);
        }
        __syncthreads();
#pragma unroll
        for (int kk = 0; kk < 32; kk++) {
            float4 av = *(float4*)&As[kk][tm << 2];
            float4 bv = *(float4*)&Bs[kk][tn << 2];
            float ar[4] = {av.x, av.y, av.z, av.w};
            float br[4] = {bv.x, bv.y, bv.z, bv.w};
#pragma unroll
            for (int i = 0; i < 4; i++)
#pragma unroll
                for (int q = 0; q < 4; q++) acc[i][q] += ar[i] * br[q];
        }
        __syncthreads();
    }
    float4 bias = *(const float4*)(bout + n0 + (tn << 2));
#pragma unroll
    for (int rm = 0; rm < 4; rm++) {
        int r = r0 + (tm << 2) + rm;
        float4 o;
        o.x = acc[rm][0] + bias.x; o.y = acc[rm][1] + bias.y;
        o.z = acc[rm][2] + bias.z; o.w = acc[rm][3] + bias.w;
        *(float4*)(out + (size_t)r * OUT_SZ + n0 + (tn << 2)) = o;
    }
}

// -------------------- launch --------------------
extern "C" void kernel_launch(void* const* d_in, const int* in_sizes, int n_in,
                              void* d_out, int out_size) {
    const float* x    = (const float*)d_in[0];
    const float* W_f  = (const float*)d_in[1];
    const float* b_f  = (const float*)d_in[2];
    const float* W_i  = (const float*)d_in[3];
    const float* b_i  = (const float*)d_in[4];
    const float* W_c  = (const float*)d_in[5];
    const float* b_c  = (const float*)d_in[6];
    const float* W_o  = (const float*)d_in[7];
    const float* b_o  = (const float*)d_in[8];
    const float* W_out= (const float*)d_in[9];
    const float* bout = (const float*)d_in[10];
    float* out = (float*)d_out;

    pack_w<<<(1536 * G4 + 255) / 256, 256>>>(W_f, W_i, W_c, W_o);
    pack_misc<<<(HID * OUT_SZ + 255) / 256, 256>>>(b_f, b_i, b_c, b_o, W_out);
    xproj_kernel<<<dim3(G4 / 64, NROWS / 64), 256>>>(x);
    lstm_kernel<<<LSTM_BLOCKS, 256>>>();
    out_kernel<<<dim3(OUT_SZ / 64, NROWS / 64), 256>>>(out, bout);
}